// round 5
// baseline (speedup 1.0000x reference)
#include <cuda_runtime.h>

// Problem shape (fixed for this instance)
#define B_ 64
#define S_ 1024
#define L_ 16
#define T_ 32
#define NSEG 64            // S_ / L_
#define AROW 20            // padded row stride (floats) for the 16x16 matrices
#define MSLOT (AROW * 16)  // 320 floats per matrix slot

#define LOG2E 1.4426950408889634f
#define LN2   0.6931471805599453f

// Scratch (static __device__ arrays — allocation-free per harness rules)
__device__ __align__(16) float g_w  [B_ * S_ * L_];    // w[b][e][k] = sum_t exp(tr[b,e,k,t])
__device__ __align__(16) float g_nc [B_ * S_];         // nc[b][e]  = tr[b,e,0,tags[b,e]]
__device__ __align__(16) float g_P  [B_ * 8 * 256];    // 128-step chunk matrices
__device__ __align__(16) float g_A0t[B_ * 8 * 256];    // level-0 matrices of the tail chunk
__device__             int   g_CP [B_ * 8];            // chunk scale exponents
__device__             int   g_C0t[B_ * 8];            // tail-chunk level-0 exponents

__device__ __forceinline__ float ex2f_(float x) {
    float r; asm("ex2.approx.f32 %0, %1;" : "=f"(r) : "f"(x)); return r;
}
__device__ __forceinline__ float lg2f_(float x) {
    float r; asm("lg2.approx.f32 %0, %1;" : "=f"(r) : "f"(x)); return r;
}
__device__ __forceinline__ int clampd_(int d) {
    return d < -120 ? -120 : (d > 120 ? 120 : d);
}
__device__ __forceinline__ int expo_(float x) {
    return (__float_as_int(x) >> 23) & 255;
}

// ---------------------------------------------------------------------------
// Kernel A: one warp per (b,e) pair — w[k] = sum_t exp(tr[k,t]) plus the
// numerator gather. Streaming loads: tr is read exactly once. DRAM-bound.
// ---------------------------------------------------------------------------
__global__ __launch_bounds__(256) void semicrf_rowsum(
    const float* __restrict__ tr,
    const int*   __restrict__ tags,
    float*       __restrict__ out)
{
    if (blockIdx.x == 0 && threadIdx.x == 0) out[0] = 0.0f;

    const int wid  = (blockIdx.x * 256 + threadIdx.x) >> 5;   // (b*S + e)
    const int lane = threadIdx.x & 31;
    const float4* base = reinterpret_cast<const float4*>(tr) + (size_t)wid * 128;
    const int sub = lane >> 3;

    float rs[4];
#pragma unroll
    for (int i = 0; i < 4; i++) {
        float4 v = __ldcs(&base[i * 32 + lane]);
        float s = ex2f_(v.x * LOG2E) + ex2f_(v.y * LOG2E)
                + ex2f_(v.z * LOG2E) + ex2f_(v.w * LOG2E);
        s += __shfl_xor_sync(0xffffffffu, s, 1);
        s += __shfl_xor_sync(0xffffffffu, s, 2);
        s += __shfl_xor_sync(0xffffffffu, s, 4);
        rs[i] = s;
    }
    if ((lane & 7) == 0) {
        float* wb = g_w + (size_t)wid * 16;
#pragma unroll
        for (int i = 0; i < 4; i++) wb[i * 4 + sub] = rs[i];
    }
    if (lane == 0) {
        int tag = tags[wid];
        g_nc[wid] = tr[(size_t)wid * 512 + tag];
    }
}

// ---------------------------------------------------------------------------
// 16x16 matrix product D = Am * Bm, one column (hl) per 16-lane group.
// Row-major, row stride AROW. Result max-normalized to ~2^0. D may alias Bm
// (all stores happen after all loads; warp-lockstep + per-lane program order).
// ---------------------------------------------------------------------------
__device__ __forceinline__ void matmul16(
    const float* Am, const float* Bm, float* Dst,
    int Ca, int Cb, int* Cdst, int hl)
{
    float bc[16];
#pragma unroll
    for (int k = 0; k < 16; k++) bc[k] = Bm[k * AROW + hl];

    float r[16];
#pragma unroll
    for (int i = 0; i < 16; i++) {
        const float4* ar = reinterpret_cast<const float4*>(Am + i * AROW);
        float4 a0 = ar[0], a1 = ar[1], a2 = ar[2], a3 = ar[3];
        float s0 = a0.x * bc[0];
        s0 = fmaf(a0.y, bc[1], s0); s0 = fmaf(a0.z, bc[2], s0); s0 = fmaf(a0.w, bc[3], s0);
        float s1 = a1.x * bc[4];
        s1 = fmaf(a1.y, bc[5], s1); s1 = fmaf(a1.z, bc[6], s1); s1 = fmaf(a1.w, bc[7], s1);
        float s2 = a2.x * bc[8];
        s2 = fmaf(a2.y, bc[9], s2); s2 = fmaf(a2.z, bc[10], s2); s2 = fmaf(a2.w, bc[11], s2);
        float s3 = a3.x * bc[12];
        s3 = fmaf(a3.y, bc[13], s3); s3 = fmaf(a3.z, bc[14], s3); s3 = fmaf(a3.w, bc[15], s3);
        r[i] = (s0 + s1) + (s2 + s3);
    }

    int ex = 0;
#pragma unroll
    for (int i = 0; i < 16; i++) ex = max(ex, expo_(r[i]));
    ex = max(ex, __shfl_xor_sync(0xffffffffu, ex, 1, 16));
    ex = max(ex, __shfl_xor_sync(0xffffffffu, ex, 2, 16));
    ex = max(ex, __shfl_xor_sync(0xffffffffu, ex, 4, 16));
    ex = max(ex, __shfl_xor_sync(0xffffffffu, ex, 8, 16));
    int d = clampd_(ex - 127);
    float sc = __int_as_float((127 - d) << 23);
#pragma unroll
    for (int i = 0; i < 16; i++) Dst[i * AROW + hl] = r[i] * sc;
    if (hl == 0) *Cdst = Ca + Cb + d;
}

// Serial matvec: vf <- normalize(M * vf); row hl per lane, vf replicated on
// all 32 lanes (halves mirror via width-16 shfl).
__device__ __forceinline__ void matvec16(
    const float* __restrict__ M, int Cm, float* vf, int& Cv, int hl)
{
    const float4* rp = reinterpret_cast<const float4*>(M + hl * AROW);
    float4 c0 = rp[0], c1 = rp[1], c2 = rp[2], c3 = rp[3];
    float a0 = c0.x * vf[0];
    a0 = fmaf(c0.y, vf[1], a0); a0 = fmaf(c0.z, vf[2], a0); a0 = fmaf(c0.w, vf[3], a0);
    float a1 = c1.x * vf[4];
    a1 = fmaf(c1.y, vf[5], a1); a1 = fmaf(c1.z, vf[6], a1); a1 = fmaf(c1.w, vf[7], a1);
    float a2 = c2.x * vf[8];
    a2 = fmaf(c2.y, vf[9], a2); a2 = fmaf(c2.z, vf[10], a2); a2 = fmaf(c2.w, vf[11], a2);
    float a3 = c3.x * vf[12];
    a3 = fmaf(c3.y, vf[13], a3); a3 = fmaf(c3.z, vf[14], a3); a3 = fmaf(c3.w, vf[15], a3);
    float s = (a0 + a1) + (a2 + a3);
#pragma unroll
    for (int k = 0; k < 16; k++) vf[k] = __shfl_sync(0xffffffffu, s, k, 16);
    int ex = 0;
#pragma unroll
    for (int k = 0; k < 16; k++) ex = max(ex, expo_(vf[k]));
    int d = clampd_(ex - 127);
    Cv += d + Cm;
    float sc = __int_as_float((127 - d) << 23);
#pragma unroll
    for (int k = 0; k < 16; k++) vf[k] *= sc;
}

// ---------------------------------------------------------------------------
// Kernel CHUNK: 512 blocks (8 chunks x 64 batches), 256 threads. Build 8
// level-0 matrices in parallel (one per half-warp), fold 8->1 in-place in
// SMEM, store the 128-step chunk matrix. The block owning the batch's tail
// chunk also stores its level-0 matrices for the scan.
// ---------------------------------------------------------------------------
__global__ __launch_bounds__(256) void semicrf_chunk(const int* __restrict__ lens)
{
    __shared__ float sA[8 * MSLOT];
    __shared__ int   sC[8];

    const int b    = blockIdx.x >> 3;
    const int c    = blockIdx.x & 7;
    const int tid  = threadIdx.x;
    const int warp = tid >> 5;
    const int lane = tid & 31;
    const int half = lane >> 4;
    const int hl   = lane & 15;

    const int len  = lens[b];
    const int m    = len >> 4;
    const int qc   = m >> 3;
    const int tseg = m & 7;

    // ---- stage 8 segments of w (2048 floats) ----
    {
        const float4* src = reinterpret_cast<const float4*>(
            g_w + ((size_t)b * S_ + c * 128) * 16);
        int f = tid;
#pragma unroll
        for (int rep = 0; rep < 2; rep++, f += 256) {
            int sl = f >> 6, off = f & 63;
            reinterpret_cast<float4*>(sA + sl * MSLOT)[off] = src[f];
        }
    }
    __syncthreads();

    // ---- build 1 level-0 matrix per half-warp (warps 0-3) ----
    if (warp < 4) {
        const int segl = warp * 2 + half;
        float* slot = sA + segl * MSLOT;
        const float4* wv = reinterpret_cast<const float4*>(slot);

        float zz[16];
#pragma unroll
        for (int k = 0; k < 16; k++) zz[k] = (k == ((16 - hl) & 15)) ? 1.0f : 0.0f;

        int C = 0;
#pragma unroll
        for (int s = 0; s < 16; s++) {
            float4 rr0 = wv[s * 4 + 0], rr1 = wv[s * 4 + 1];
            float4 rr2 = wv[s * 4 + 2], rr3 = wv[s * 4 + 3];

            float p3 = zz[(s - 15 + 32) & 15] * rr3.w;
            p3 = fmaf(zz[(s - 14 + 32) & 15], rr3.z, p3);
            p3 = fmaf(zz[(s - 13 + 32) & 15], rr3.y, p3);
            p3 = fmaf(zz[(s - 12 + 32) & 15], rr3.x, p3);
            float p2 = zz[(s - 11 + 32) & 15] * rr2.w;
            p2 = fmaf(zz[(s - 10 + 32) & 15], rr2.z, p2);
            p2 = fmaf(zz[(s -  9 + 32) & 15], rr2.y, p2);
            p2 = fmaf(zz[(s -  8 + 32) & 15], rr2.x, p2);
            float p1 = zz[(s -  7 + 32) & 15] * rr1.w;
            p1 = fmaf(zz[(s -  6 + 32) & 15], rr1.z, p1);
            p1 = fmaf(zz[(s -  5 + 32) & 15], rr1.y, p1);
            p1 = fmaf(zz[(s -  4 + 32) & 15], rr1.x, p1);
            float p0 = zz[(s -  3 + 32) & 15] * rr0.w;
            p0 = fmaf(zz[(s -  2 + 32) & 15], rr0.z, p0);
            p0 = fmaf(zz[(s -  1 + 32) & 15], rr0.y, p0);

            float zn = ((p3 + p2) + p1) + p0;
            zn = fmaf(zz[s & 15], rr0.x, zn);
            zz[(s + 1) & 15] = zn;

            if ((s & 3) == 3 && s != 15) {
                int ex = expo_(zn);
                ex = max(ex, __shfl_xor_sync(0xffffffffu, ex, 1, 16));
                ex = max(ex, __shfl_xor_sync(0xffffffffu, ex, 2, 16));
                ex = max(ex, __shfl_xor_sync(0xffffffffu, ex, 4, 16));
                ex = max(ex, __shfl_xor_sync(0xffffffffu, ex, 8, 16));
                int d = clampd_(ex - 127);
                C += d;
                float sc = __int_as_float((127 - d) << 23);
#pragma unroll
                for (int k2 = 0; k2 < 16; k2++) zz[k2] *= sc;
            }
        }

        // final renorm: true matrix max -> ~2^0
        {
            int ex = 0;
#pragma unroll
            for (int k = 0; k < 16; k++) ex = max(ex, expo_(zz[k]));
            ex = max(ex, __shfl_xor_sync(0xffffffffu, ex, 1, 16));
            ex = max(ex, __shfl_xor_sync(0xffffffffu, ex, 2, 16));
            ex = max(ex, __shfl_xor_sync(0xffffffffu, ex, 4, 16));
            ex = max(ex, __shfl_xor_sync(0xffffffffu, ex, 8, 16));
            int d = clampd_(ex - 127);
            C += d;
            float sc = __int_as_float((127 - d) << 23);
#pragma unroll
            for (int k = 0; k < 16; k++) zz[k] *= sc;
        }

        __syncwarp();   // all w reads of this slot complete before overwrite
#pragma unroll
        for (int i = 0; i < 16; i++) slot[i * AROW + hl] = zz[(16 - i) & 15];
        if (hl == 0) sC[segl] = C;

        // tail chunk: store level-0 matrices needed by the scan
        if (c == qc && segl < tseg) {
            float* gd = g_A0t + ((size_t)b * 8 + segl) * 256;
#pragma unroll
            for (int i = 0; i < 16; i++) gd[i * 16 + hl] = zz[(16 - i) & 15];
            if (hl == 0) g_C0t[b * 8 + segl] = C;
        }
    }
    __syncthreads();

    // ---- fold 8 -> 4 -> 2 -> 1, in place ----
    if (warp < 2) {   // level 1: 4 products
        int u = warp * 2 + half;
        matmul16(sA + (2 * u + 1) * MSLOT, sA + (2 * u) * MSLOT,
                 sA + (2 * u) * MSLOT, sC[2 * u + 1], sC[2 * u], &sC[2 * u], hl);
    }
    __syncthreads();
    if (warp == 0) {  // level 2: 2 products (one per half-warp)
        int u = half;
        matmul16(sA + (4 * u + 2) * MSLOT, sA + (4 * u) * MSLOT,
                 sA + (4 * u) * MSLOT, sC[4 * u + 2], sC[4 * u], &sC[4 * u], hl);
    }
    __syncthreads();
    if (warp == 0) {  // level 3: 1 product (both halves redundant, benign)
        matmul16(sA + 4 * MSLOT, sA, sA, sC[4], sC[0], &sC[0], hl);
    }
    __syncthreads();

    // ---- store chunk matrix (one element per thread) ----
    {
        float* gp = g_P + ((size_t)b * 8 + c) * 256;
        gp[tid] = sA[(tid >> 4) * AROW + (tid & 15)];
        if (tid == 0) g_CP[b * 8 + c] = sC[0];
    }
}

// ---------------------------------------------------------------------------
// Kernel SCAN: 64 blocks x 128 threads. Stage all needed matrices + tail w
// + numerator into SMEM in one parallel burst; warp 0 runs the short serial
// chain (<=15 matvecs + <=15 raw steps).
// ---------------------------------------------------------------------------
__global__ __launch_bounds__(128) void semicrf_scan(
    const int* __restrict__ lens,
    float*     __restrict__ out)
{
    __shared__ float sM[15 * MSLOT];
    __shared__ int   sCm[15];
    __shared__ float sTail[256];
    __shared__ float sNum[4];

    const int b    = blockIdx.x;
    const int tid  = threadIdx.x;
    const int warp = tid >> 5;
    const int lane = tid & 31;
    const int hl   = lane & 15;

    const int len  = lens[b];
    const int m    = len >> 4;
    const int rem  = len & 15;
    const int qc   = m >> 3;
    const int tseg = m & 7;
    const int n_m  = qc + tseg;

    // numerator partials
    {
        float np = 0.0f;
        const float* ncb = g_nc + (size_t)b * S_;
        for (int e = tid; e < len; e += 128) np += ncb[e];
#pragma unroll
        for (int o = 16; o > 0; o >>= 1) np += __shfl_xor_sync(0xffffffffu, np, o);
        if (lane == 0) sNum[warp] = np;
    }

    // stage matrices (padded) — chunks first, then tail-chunk level-0s
    for (int idx = tid; idx < n_m * 256; idx += 128) {
        int j = idx >> 8, pos = idx & 255;
        const float* src = (j < qc)
            ? g_P   + ((size_t)b * 8 + j) * 256
            : g_A0t + ((size_t)b * 8 + (j - qc)) * 256;
        sM[j * MSLOT + (pos >> 4) * AROW + (pos & 15)] = src[pos];
    }
    if (tid < n_m)
        sCm[tid] = (tid < qc) ? g_CP[b * 8 + tid] : g_C0t[b * 8 + (tid - qc)];

    // tail w staging
    if (rem > 0 && tid < 64) {
        reinterpret_cast<float4*>(sTail)[tid] = reinterpret_cast<const float4*>(
            g_w + ((size_t)b * S_ + m * 16) * 16)[tid];
    }
    __syncthreads();

    if (warp == 0) {
        float vf[16];
#pragma unroll
        for (int k = 0; k < 16; k++) vf[k] = (k == 0) ? 1.0f : 0.0f;
        int Cv = 0;

        for (int j = 0; j < n_m; j++)
            matvec16(sM + j * MSLOT, sCm[j], vf, Cv, hl);

        float den = ((float)Cv + lg2f_(vf[0])) * LN2;   // covers rem == 0
        if (rem > 0) {
            float zz[16];
#pragma unroll
            for (int j = 0; j < 16; j++) zz[j] = vf[(16 - j) & 15];
            const float4* wb = reinterpret_cast<const float4*>(sTail);
#pragma unroll
            for (int s2 = 0; s2 < 15; s2++) {
                if (s2 < rem) {
                    float4 rr0 = wb[s2 * 4 + 0], rr1 = wb[s2 * 4 + 1];
                    float4 rr2 = wb[s2 * 4 + 2], rr3 = wb[s2 * 4 + 3];

                    float p3 = zz[(s2 - 15 + 32) & 15] * rr3.w;
                    p3 = fmaf(zz[(s2 - 14 + 32) & 15], rr3.z, p3);
                    p3 = fmaf(zz[(s2 - 13 + 32) & 15], rr3.y, p3);
                    p3 = fmaf(zz[(s2 - 12 + 32) & 15], rr3.x, p3);
                    float p2 = zz[(s2 - 11 + 32) & 15] * rr2.w;
                    p2 = fmaf(zz[(s2 - 10 + 32) & 15], rr2.z, p2);
                    p2 = fmaf(zz[(s2 -  9 + 32) & 15], rr2.y, p2);
                    p2 = fmaf(zz[(s2 -  8 + 32) & 15], rr2.x, p2);
                    float p1 = zz[(s2 -  7 + 32) & 15] * rr1.w;
                    p1 = fmaf(zz[(s2 -  6 + 32) & 15], rr1.z, p1);
                    p1 = fmaf(zz[(s2 -  5 + 32) & 15], rr1.y, p1);
                    p1 = fmaf(zz[(s2 -  4 + 32) & 15], rr1.x, p1);
                    float p0 = zz[(s2 -  3 + 32) & 15] * rr0.w;
                    p0 = fmaf(zz[(s2 -  2 + 32) & 15], rr0.z, p0);
                    p0 = fmaf(zz[(s2 -  1 + 32) & 15], rr0.y, p0);

                    float zn = ((p3 + p2) + p1) + p0;
                    zn = fmaf(zz[s2 & 15], rr0.x, zn);

                    if (s2 == rem - 1) den = ((float)Cv + lg2f_(zn)) * LN2;

                    zz[(s2 + 1) & 15] = zn;

                    if ((s2 & 1) == 1) {   // uniform renorm (all lanes identical)
                        int d2 = clampd_(expo_(zn) - 127);
                        Cv += d2;
                        float sc2 = __int_as_float((127 - d2) << 23);
#pragma unroll
                        for (int k2 = 0; k2 < 16; k2++) zz[k2] *= sc2;
                    }
                }
            }
        }

        float nt = (lane < 4) ? sNum[lane] : 0.0f;
#pragma unroll
        for (int o = 2; o > 0; o >>= 1) nt += __shfl_xor_sync(0xffffffffu, nt, o);
        nt = __shfl_sync(0xffffffffu, nt, 0);

        if (lane == 0) atomicAdd(out, den - nt);
    }
}

// ---------------------------------------------------------------------------
extern "C" void kernel_launch(void* const* d_in, const int* in_sizes, int n_in,
                              void* d_out, int out_size)
{
    const float* tr   = (const float*)d_in[0];   // [B,S,L,T] f32
    const int*   tags = (const int*)  d_in[1];   // [B,S] i32
    const int*   lens = (const int*)  d_in[2];   // [B] i32
    float*       out  = (float*)d_out;           // scalar f32

    semicrf_rowsum<<<8192, 256>>>(tr, tags, out);   // DRAM-bound pass over tr
    semicrf_chunk<<<512, 256>>>(lens);              // 8 chunks x 64 batches
    semicrf_scan<<<64, 128>>>(lens, out);           // short serial chain
}